// round 11
// baseline (speedup 1.0000x reference)
#include <cuda_runtime.h>
#include <cuda_fp16.h>
#include <cstdint>

#define N_NODES 300000
#define N_EDGES 600000
#define N_GRAPHS 12000
#define HID 128
#define F_ATOM 9
#define V_ATOM 119
#define D_ATOM 9
#define EMB_SZ (F_ATOM * V_ATOM * D_ATOM)   // 9639 floats

#define SCAN_E 1024
#define NSB ((N_NODES + SCAN_E - 1) / SCAN_E)   // 293

// ---------------- scratch (device globals; no allocations allowed) ----------
__device__ __half g_h1h[(size_t)N_NODES * HID];   // h1 (fp16)
__device__ __half g_a1h[(size_t)N_NODES * HID];   // relu(agg1) (fp16)
__device__ int    g_deg[N_NODES];
__device__ float  g_dinv[N_NODES];
__device__ int    g_rowptr[N_NODES + 1];
__device__ int    g_fill[N_NODES];
__device__ uint2  g_csre[N_EDGES];                // (src, coef-bits)
__device__ int    g_bsum[NSB];
__device__ float  g_cnt[N_GRAPHS];
__device__ float  g_pool[N_GRAPHS * HID];
__device__ float  g_wc[HID * HID];
__device__ float  g_bc[HID];

// ---------------- degree (edges only; dst via int4) -------------------------
__global__ void k_deg(const int* __restrict__ ei) {
    int i = blockIdx.x * blockDim.x + threadIdx.x;
    int stride = gridDim.x * blockDim.x;
    const int NV = N_EDGES / 4;
    const int4* dst4 = (const int4*)(ei + N_EDGES);
    for (int j = i; j < NV; j += stride) {
        int4 d = __ldg(&dst4[j]);
        atomicAdd(&g_deg[d.x], 1);
        atomicAdd(&g_deg[d.y], 1);
        atomicAdd(&g_deg[d.z], 1);
        atomicAdd(&g_deg[d.w], 1);
    }
}

// ---------------- per-graph node counts (stream A) ---------------------------
__global__ void k_cnt(const int* __restrict__ batch) {
    int i = blockIdx.x * blockDim.x + threadIdx.x;
    int stride = gridDim.x * blockDim.x;
    for (int n = i; n < N_NODES; n += stride)
        atomicAdd(&g_cnt[batch[n]], 1.f);
}

// ---------------- scan part 1 ------------------------------------------------
__global__ void k_scan1() {
    __shared__ int s[256];
    int t = threadIdx.x;
    int base = blockIdx.x * SCAN_E + t * 4;
    int v[4];
#pragma unroll
    for (int k = 0; k < 4; k++) v[k] = (base + k < N_NODES) ? g_deg[base + k] : 0;
    v[1] += v[0]; v[2] += v[1]; v[3] += v[2];
    s[t] = v[3];
    __syncthreads();
    for (int off = 1; off < 256; off <<= 1) {
        int add = (t >= off) ? s[t - off] : 0;
        __syncthreads();
        s[t] += add;
        __syncthreads();
    }
    int pre = (t > 0) ? s[t - 1] : 0;
#pragma unroll
    for (int k = 0; k < 4; k++)
        if (base + k < N_NODES) g_rowptr[base + k + 1] = v[k] + pre;
    if (t == 255) g_bsum[blockIdx.x] = s[255];
}

// ---------------- scan parts 2+3 fused ---------------------------------------
__global__ void __launch_bounds__(512) k_scan23() {
    __shared__ int s[512];
    int t = threadIdx.x;
    s[t] = (t < NSB) ? g_bsum[t] : 0;
    __syncthreads();
    for (int off = 1; off < 512; off <<= 1) {
        int v = (t >= off) ? s[t - off] : 0;
        __syncthreads();
        s[t] += v;
        __syncthreads();
    }
    int i = blockIdx.x * 512 + t;
    if (i >= N_NODES) return;
    int blk = i / SCAN_E;
    int add = (blk > 0) ? s[blk - 1] : 0;
    int incl = g_rowptr[i + 1] + add;
    g_rowptr[i + 1] = incl;
    int d = g_deg[i];
    g_fill[i] = incl - d;
    g_dinv[i] = rsqrtf((float)d + 1.0f);
    if (i == 0) g_rowptr[0] = 0;
}

// ---------------- scatter edges into CSR with precomputed coef ---------------
__global__ void k_scatter(const int* __restrict__ ei) {
    int e = blockIdx.x * blockDim.x + threadIdx.x;
    if (e >= N_EDGES) return;
    int src = __ldg(&ei[e]);
    int dst = __ldg(&ei[N_EDGES + e]);
    float c = __ldg(&g_dinv[src]) * __ldg(&g_dinv[dst]);
    int pos = atomicAdd(&g_fill[dst], 1);
    g_csre[pos] = make_uint2((unsigned)src, __float_as_uint(c));
}

// ---------------- embed + h1 = h0@W1 (fp16 out) ------------------------------
__global__ void __launch_bounds__(256) k_embed(const int* __restrict__ x,
                                               const float* __restrict__ emb,
                                               const float* __restrict__ W1) {
    __shared__ float s_emb[EMB_SZ];
    __shared__ float s_h0[8][16];
    int tid = threadIdx.x;
    for (int i = tid; i < EMB_SZ; i += 256) s_emb[i] = emb[i];

    int warp = tid >> 5, lane = tid & 31;
    float4 w[D_ATOM];
    const float4* W1v = (const float4*)W1;
#pragma unroll
    for (int d = 0; d < D_ATOM; d++) w[d] = W1v[d * (HID / 4) + lane];
    __syncthreads();

    int gwarp = blockIdx.x * 8 + warp;
    const int NW = 592 * 8;
    for (int n = gwarp; n < N_NODES; n += NW) {
        int xv = 0;
        if (lane < F_ATOM) xv = __ldg(&x[n * F_ATOM + lane]);
        int xf[F_ATOM];
#pragma unroll
        for (int f = 0; f < F_ATOM; f++) xf[f] = __shfl_sync(0xffffffffu, xv, f);

        if (lane < D_ATOM) {
            float h = 0.f;
#pragma unroll
            for (int f = 0; f < F_ATOM; f++)
                h += s_emb[(f * V_ATOM + xf[f]) * D_ATOM + lane];
            s_h0[warp][lane] = h;
        }
        __syncwarp();
        float4 acc = make_float4(0.f, 0.f, 0.f, 0.f);
#pragma unroll
        for (int d = 0; d < D_ATOM; d++) {
            float h = s_h0[warp][d];
            acc.x += h * w[d].x; acc.y += h * w[d].y;
            acc.z += h * w[d].z; acc.w += h * w[d].w;
        }
        __syncwarp();

        __half2 p0 = __floats2half2_rn(acc.x, acc.y);
        __half2 p1 = __floats2half2_rn(acc.z, acc.w);
        uint2 u;
        u.x = *reinterpret_cast<unsigned*>(&p0);
        u.y = *reinterpret_cast<unsigned*>(&p1);
        ((uint2*)(g_h1h + (size_t)n * HID))[lane] = u;
    }
}

// ---------------- helpers ----------------------------------------------------
__device__ __forceinline__ float4 unpack_h4(uint2 u) {
    __half2 a = *reinterpret_cast<__half2*>(&u.x);
    __half2 b = *reinterpret_cast<__half2*>(&u.y);
    float2 fa = __half22float2(a), fb = __half22float2(b);
    return make_float4(fa.x, fa.y, fb.x, fb.y);
}

// ---------------- pass1: relu(agg1) = relu(Â h1 + b1) -> g_a1h ---------------
// Full warp per node (uniform loop), coef precomputed in CSR.
__global__ void __launch_bounds__(256) k_pass1(const float* __restrict__ b1) {
    int n = blockIdx.x * 8 + (threadIdx.x >> 5);
    if (n >= N_NODES) return;
    int lane = threadIdx.x & 31;

    int r0 = __ldg(&g_rowptr[n]);
    int r1 = __ldg(&g_rowptr[n + 1]);
    float dn = __ldg(&g_dinv[n]);
    float s = dn * dn;

    uint2 u = __ldg(((const uint2*)(g_h1h + (size_t)n * HID)) + lane);
    float4 v = unpack_h4(u);
    float4 bb = __ldg(((const float4*)b1) + lane);
    float4 acc = make_float4(v.x * s + bb.x, v.y * s + bb.y,
                             v.z * s + bb.z, v.w * s + bb.w);

    uint2 en = (r0 < r1) ? __ldg(&g_csre[r0]) : make_uint2(0u, 0u);
    for (int j = r0; j < r1; j++) {
        uint2 e = en;
        if (j + 1 < r1) en = __ldg(&g_csre[j + 1]);
        float c = __uint_as_float(e.y);
        uint2 us = __ldg(((const uint2*)(g_h1h + (size_t)e.x * HID)) + lane);
        float4 vs = unpack_h4(us);
        acc.x += vs.x * c; acc.y += vs.y * c;
        acc.z += vs.z * c; acc.w += vs.w * c;
    }

    acc.x = fmaxf(acc.x, 0.f); acc.y = fmaxf(acc.y, 0.f);
    acc.z = fmaxf(acc.z, 0.f); acc.w = fmaxf(acc.w, 0.f);
    __half2 p0 = __floats2half2_rn(acc.x, acc.y);
    __half2 p1 = __floats2half2_rn(acc.z, acc.w);
    uint2* op = ((uint2*)(g_a1h + (size_t)n * HID)) + lane;
    asm volatile("st.global.cs.v2.u32 [%0], {%1,%2};"
                 :: "l"(op),
                    "r"(*reinterpret_cast<unsigned*>(&p0)),
                    "r"(*reinterpret_cast<unsigned*>(&p1))
                 : "memory");
}

// ---------------- pass2 fused with pooling -----------------------------------
__global__ void __launch_bounds__(256) k_pass2(const int* __restrict__ batch) {
    int n = blockIdx.x * 8 + (threadIdx.x >> 5);
    if (n >= N_NODES) return;
    int lane = threadIdx.x & 31;

    int r0 = __ldg(&g_rowptr[n]);
    int r1 = __ldg(&g_rowptr[n + 1]);
    float dn = __ldg(&g_dinv[n]);
    float s = dn * dn;
    int g = __ldg(&batch[n]);

    uint2 u = __ldg(((const uint2*)(g_a1h + (size_t)n * HID)) + lane);
    float4 v = unpack_h4(u);
    float4 acc = make_float4(v.x * s, v.y * s, v.z * s, v.w * s);

    uint2 en = (r0 < r1) ? __ldg(&g_csre[r0]) : make_uint2(0u, 0u);
    for (int j = r0; j < r1; j++) {
        uint2 e = en;
        if (j + 1 < r1) en = __ldg(&g_csre[j + 1]);
        float c = __uint_as_float(e.y);
        uint2 us = __ldg(((const uint2*)(g_a1h + (size_t)e.x * HID)) + lane);
        float4 vs = unpack_h4(us);
        acc.x += vs.x * c; acc.y += vs.y * c;
        acc.z += vs.z * c; acc.w += vs.w * c;
    }

    float* pp = g_pool + (size_t)g * HID + lane * 4;
    asm volatile("red.global.add.v4.f32 [%0], {%1,%2,%3,%4};"
                 :: "l"(pp), "f"(acc.x), "f"(acc.y), "f"(acc.z), "f"(acc.w)
                 : "memory");
}

// ---------------- Wc = W2 @ Wfc ; Bc = b2 @ Wfc + bfc -----------------------
__global__ void k_wc(const float* __restrict__ W2, const float* __restrict__ Wfc,
                     const float* __restrict__ b2, const float* __restrict__ bfc) {
    int i = blockIdx.x;
    int j = threadIdx.x;
    float acc = 0.f;
    for (int k = 0; k < HID; k++) acc += W2[i * HID + k] * Wfc[k * HID + j];
    g_wc[i * HID + j] = acc;
    if (i == 0) {
        float a = bfc[j];
        for (int k = 0; k < HID; k++) a += b2[k] * Wfc[k * HID + j];
        g_bc[j] = a;
    }
}

// ---------------- final: out = (pool/cnt) @ Wc + Bc -------------------------
__global__ void k_out(float* __restrict__ out) {
    __shared__ float p[HID];
    int g = blockIdx.x;
    int c = threadIdx.x;
    float cnt = fmaxf(g_cnt[g], 1.f);
    p[c] = g_pool[g * HID + c] / cnt;
    __syncthreads();
    float acc = g_bc[c];
#pragma unroll 8
    for (int k = 0; k < HID; k++) acc += p[k] * g_wc[k * HID + c];
    out[g * HID + c] = acc;
}

// ---------------- launch: fork-join two-stream graph -------------------------
extern "C" void kernel_launch(void* const* d_in, const int* in_sizes, int n_in,
                              void* d_out, int out_size) {
    const int*   x     = (const int*)d_in[0];
    const int*   ei    = (const int*)d_in[1];
    const int*   batch = (const int*)d_in[3];
    const float* aemb  = (const float*)d_in[4];
    const float* W1    = (const float*)d_in[6];
    const float* b1    = (const float*)d_in[7];
    const float* W2    = (const float*)d_in[8];
    const float* b2    = (const float*)d_in[9];
    const float* Wfc   = (const float*)d_in[10];
    const float* bfc   = (const float*)d_in[11];
    float* out = (float*)d_out;

    static cudaStream_t sA = nullptr, sB = nullptr;
    static cudaEvent_t eF = nullptr, eA = nullptr, eB = nullptr;
    static void *p_deg = nullptr, *p_pool = nullptr, *p_cnt = nullptr;
    if (sA == nullptr) {
        cudaStreamCreateWithFlags(&sA, cudaStreamNonBlocking);
        cudaStreamCreateWithFlags(&sB, cudaStreamNonBlocking);
        cudaEventCreateWithFlags(&eF, cudaEventDisableTiming);
        cudaEventCreateWithFlags(&eA, cudaEventDisableTiming);
        cudaEventCreateWithFlags(&eB, cudaEventDisableTiming);
        cudaGetSymbolAddress(&p_deg, g_deg);
        cudaGetSymbolAddress(&p_pool, g_pool);
        cudaGetSymbolAddress(&p_cnt, g_cnt);
    }

    // fork from the (captured) base stream
    cudaEventRecord(eF, 0);
    cudaStreamWaitEvent(sA, eF, 0);
    cudaStreamWaitEvent(sB, eF, 0);

    // stream A: pool/cnt zero + batch counts + embedding + weight precompute
    cudaMemsetAsync(p_pool, 0, (size_t)N_GRAPHS * HID * sizeof(float), sA);
    cudaMemsetAsync(p_cnt, 0, (size_t)N_GRAPHS * sizeof(float), sA);
    k_cnt<<<1024, 256, 0, sA>>>(batch);
    k_embed<<<592, 256, 0, sA>>>(x, aemb, W1);
    k_wc<<<HID, HID, 0, sA>>>(W2, Wfc, b2, bfc);

    // stream B: CSR build chain
    cudaMemsetAsync(p_deg, 0, (size_t)N_NODES * sizeof(int), sB);
    k_deg<<<586, 256, 0, sB>>>(ei);
    k_scan1<<<NSB, 256, 0, sB>>>();
    k_scan23<<<(N_NODES + 511) / 512, 512, 0, sB>>>();
    k_scatter<<<(N_EDGES + 255) / 256, 256, 0, sB>>>(ei);

    // join back to base stream
    cudaEventRecord(eA, sA);
    cudaEventRecord(eB, sB);
    cudaStreamWaitEvent(0, eA, 0);
    cudaStreamWaitEvent(0, eB, 0);

    k_pass1<<<(N_NODES + 7) / 8, 256>>>(b1);
    k_pass2<<<(N_NODES + 7) / 8, 256>>>(batch);
    k_out<<<N_GRAPHS, HID>>>(out);
}

// round 13
// speedup vs baseline: 1.0296x; 1.0296x over previous
#include <cuda_runtime.h>
#include <cuda_fp16.h>
#include <cstdint>

#define N_NODES 300000
#define N_EDGES 600000
#define N_GRAPHS 12000
#define HID 128
#define F_ATOM 9
#define V_ATOM 119
#define D_ATOM 9
#define EMB_SZ (F_ATOM * V_ATOM * D_ATOM)   // 9639 floats

#define SCAN_E 1024
#define NSB ((N_NODES + SCAN_E - 1) / SCAN_E)   // 293

// ---------------- scratch (device globals; no allocations allowed) ----------
__device__ __half g_h1h[(size_t)N_NODES * HID];   // h1 (fp16)
__device__ __half g_a1h[(size_t)N_NODES * HID];   // relu(agg1) (fp16)
__device__ int    g_deg[N_NODES];
__device__ float  g_dinv[N_NODES];
__device__ int    g_rowptr[N_NODES + 1];
__device__ int    g_fill[N_NODES];
__device__ uint2  g_csre[N_EDGES];                // (src, coef-bits)
__device__ int    g_bsum[NSB];
__device__ float  g_cnt[N_GRAPHS];
__device__ float  g_pool[N_GRAPHS * HID];
__device__ float  g_wc[HID * HID];
__device__ float  g_bc[HID];

// ---------------- degree (edges only; dst via int4) -------------------------
__global__ void k_deg(const int* __restrict__ ei) {
    int i = blockIdx.x * blockDim.x + threadIdx.x;
    int stride = gridDim.x * blockDim.x;
    const int NV = N_EDGES / 4;
    const int4* dst4 = (const int4*)(ei + N_EDGES);
    for (int j = i; j < NV; j += stride) {
        int4 d = __ldg(&dst4[j]);
        atomicAdd(&g_deg[d.x], 1);
        atomicAdd(&g_deg[d.y], 1);
        atomicAdd(&g_deg[d.z], 1);
        atomicAdd(&g_deg[d.w], 1);
    }
}

// ---------------- per-graph node counts (stream C) ---------------------------
__global__ void k_cnt(const int* __restrict__ batch) {
    int i = blockIdx.x * blockDim.x + threadIdx.x;
    int stride = gridDim.x * blockDim.x;
    for (int n = i; n < N_NODES; n += stride)
        atomicAdd(&g_cnt[batch[n]], 1.f);
}

// ---------------- scan part 1 ------------------------------------------------
__global__ void k_scan1() {
    __shared__ int s[256];
    int t = threadIdx.x;
    int base = blockIdx.x * SCAN_E + t * 4;
    int v[4];
#pragma unroll
    for (int k = 0; k < 4; k++) v[k] = (base + k < N_NODES) ? g_deg[base + k] : 0;
    v[1] += v[0]; v[2] += v[1]; v[3] += v[2];
    s[t] = v[3];
    __syncthreads();
    for (int off = 1; off < 256; off <<= 1) {
        int add = (t >= off) ? s[t - off] : 0;
        __syncthreads();
        s[t] += add;
        __syncthreads();
    }
    int pre = (t > 0) ? s[t - 1] : 0;
#pragma unroll
    for (int k = 0; k < 4; k++)
        if (base + k < N_NODES) g_rowptr[base + k + 1] = v[k] + pre;
    if (t == 255) g_bsum[blockIdx.x] = s[255];
}

// ---------------- scan parts 2+3 fused ---------------------------------------
__global__ void __launch_bounds__(512) k_scan23() {
    __shared__ int s[512];
    int t = threadIdx.x;
    s[t] = (t < NSB) ? g_bsum[t] : 0;
    __syncthreads();
    for (int off = 1; off < 512; off <<= 1) {
        int v = (t >= off) ? s[t - off] : 0;
        __syncthreads();
        s[t] += v;
        __syncthreads();
    }
    int i = blockIdx.x * 512 + t;
    if (i >= N_NODES) return;
    int blk = i / SCAN_E;
    int add = (blk > 0) ? s[blk - 1] : 0;
    int incl = g_rowptr[i + 1] + add;
    g_rowptr[i + 1] = incl;
    int d = g_deg[i];
    g_fill[i] = incl - d;
    g_dinv[i] = rsqrtf((float)d + 1.0f);
    if (i == 0) g_rowptr[0] = 0;
}

// ---------------- scatter edges into CSR with precomputed coef ---------------
__global__ void k_scatter(const int* __restrict__ ei) {
    int e = blockIdx.x * blockDim.x + threadIdx.x;
    if (e >= N_EDGES) return;
    int src = __ldg(&ei[e]);
    int dst = __ldg(&ei[N_EDGES + e]);
    float c = __ldg(&g_dinv[src]) * __ldg(&g_dinv[dst]);
    int pos = atomicAdd(&g_fill[dst], 1);
    g_csre[pos] = make_uint2((unsigned)src, __float_as_uint(c));
}

// ---------------- embed + h1 = h0@W1 (fp16 out) ------------------------------
__global__ void __launch_bounds__(256) k_embed(const int* __restrict__ x,
                                               const float* __restrict__ emb,
                                               const float* __restrict__ W1) {
    __shared__ float s_emb[EMB_SZ];
    __shared__ float s_h0[8][16];
    int tid = threadIdx.x;
    for (int i = tid; i < EMB_SZ; i += 256) s_emb[i] = emb[i];

    int warp = tid >> 5, lane = tid & 31;
    float4 w[D_ATOM];
    const float4* W1v = (const float4*)W1;
#pragma unroll
    for (int d = 0; d < D_ATOM; d++) w[d] = W1v[d * (HID / 4) + lane];
    __syncthreads();

    int gwarp = blockIdx.x * 8 + warp;
    const int NW = 592 * 8;
    for (int n = gwarp; n < N_NODES; n += NW) {
        int xv = 0;
        if (lane < F_ATOM) xv = __ldg(&x[n * F_ATOM + lane]);
        int xf[F_ATOM];
#pragma unroll
        for (int f = 0; f < F_ATOM; f++) xf[f] = __shfl_sync(0xffffffffu, xv, f);

        if (lane < D_ATOM) {
            float h = 0.f;
#pragma unroll
            for (int f = 0; f < F_ATOM; f++)
                h += s_emb[(f * V_ATOM + xf[f]) * D_ATOM + lane];
            s_h0[warp][lane] = h;
        }
        __syncwarp();
        float4 acc = make_float4(0.f, 0.f, 0.f, 0.f);
#pragma unroll
        for (int d = 0; d < D_ATOM; d++) {
            float h = s_h0[warp][d];
            acc.x += h * w[d].x; acc.y += h * w[d].y;
            acc.z += h * w[d].z; acc.w += h * w[d].w;
        }
        __syncwarp();

        __half2 p0 = __floats2half2_rn(acc.x, acc.y);
        __half2 p1 = __floats2half2_rn(acc.z, acc.w);
        uint2 u;
        u.x = *reinterpret_cast<unsigned*>(&p0);
        u.y = *reinterpret_cast<unsigned*>(&p1);
        ((uint2*)(g_h1h + (size_t)n * HID))[lane] = u;
    }
}

// ---------------- helpers ----------------------------------------------------
__device__ __forceinline__ float4 unpack_h4(uint2 u) {
    __half2 a = *reinterpret_cast<__half2*>(&u.x);
    __half2 b = *reinterpret_cast<__half2*>(&u.y);
    float2 fa = __half22float2(a), fb = __half22float2(b);
    return make_float4(fa.x, fa.y, fb.x, fb.y);
}

// Accumulate one batch of up to 4 edges with all gathers issued up-front.
// Inactive slots use src=0 with coef=0 (contributes nothing, branch-free).
template <typename T>
__device__ __forceinline__ void edge_chunk4(const T* base, int lane,
                                            int j, int r1, float4& acc) {
    uint2 e0 = make_uint2(0u, 0u), e1 = e0, e2 = e0, e3 = e0;
    e0 = __ldg(&g_csre[j]);
    if (j + 1 < r1) e1 = __ldg(&g_csre[j + 1]);
    if (j + 2 < r1) e2 = __ldg(&g_csre[j + 2]);
    if (j + 3 < r1) e3 = __ldg(&g_csre[j + 3]);
    // issue all 4 row gathers back-to-back (MLP=4)
    uint2 u0 = __ldg(((const uint2*)(base + (size_t)e0.x * HID)) + lane);
    uint2 u1 = __ldg(((const uint2*)(base + (size_t)e1.x * HID)) + lane);
    uint2 u2 = __ldg(((const uint2*)(base + (size_t)e2.x * HID)) + lane);
    uint2 u3 = __ldg(((const uint2*)(base + (size_t)e3.x * HID)) + lane);
    float c0 = __uint_as_float(e0.y), c1 = __uint_as_float(e1.y);
    float c2 = __uint_as_float(e2.y), c3 = __uint_as_float(e3.y);
    float4 v0 = unpack_h4(u0), v1 = unpack_h4(u1);
    float4 v2 = unpack_h4(u2), v3 = unpack_h4(u3);
    acc.x += v0.x * c0 + v1.x * c1 + v2.x * c2 + v3.x * c3;
    acc.y += v0.y * c0 + v1.y * c1 + v2.y * c2 + v3.y * c3;
    acc.z += v0.z * c0 + v1.z * c1 + v2.z * c2 + v3.z * c3;
    acc.w += v0.w * c0 + v1.w * c1 + v2.w * c2 + v3.w * c3;
}

// ---------------- pass1: relu(agg1) = relu(Â h1 + b1) -> g_a1h ---------------
__global__ void __launch_bounds__(256) k_pass1(const float* __restrict__ b1) {
    int n = blockIdx.x * 8 + (threadIdx.x >> 5);
    if (n >= N_NODES) return;
    int lane = threadIdx.x & 31;

    int r0 = __ldg(&g_rowptr[n]);
    int r1 = __ldg(&g_rowptr[n + 1]);
    float dn = __ldg(&g_dinv[n]);
    float s = dn * dn;

    uint2 u = __ldg(((const uint2*)(g_h1h + (size_t)n * HID)) + lane);
    float4 v = unpack_h4(u);
    float4 bb = __ldg(((const float4*)b1) + lane);
    float4 acc = make_float4(v.x * s + bb.x, v.y * s + bb.y,
                             v.z * s + bb.z, v.w * s + bb.w);

    for (int j = r0; j < r1; j += 4)
        edge_chunk4(g_h1h, lane, j, r1, acc);

    acc.x = fmaxf(acc.x, 0.f); acc.y = fmaxf(acc.y, 0.f);
    acc.z = fmaxf(acc.z, 0.f); acc.w = fmaxf(acc.w, 0.f);
    __half2 p0 = __floats2half2_rn(acc.x, acc.y);
    __half2 p1 = __floats2half2_rn(acc.z, acc.w);
    uint2* op = ((uint2*)(g_a1h + (size_t)n * HID)) + lane;
    asm volatile("st.global.cs.v2.u32 [%0], {%1,%2};"
                 :: "l"(op),
                    "r"(*reinterpret_cast<unsigned*>(&p0)),
                    "r"(*reinterpret_cast<unsigned*>(&p1))
                 : "memory");
}

// ---------------- pass2 fused with pooling -----------------------------------
__global__ void __launch_bounds__(256) k_pass2(const int* __restrict__ batch) {
    int n = blockIdx.x * 8 + (threadIdx.x >> 5);
    if (n >= N_NODES) return;
    int lane = threadIdx.x & 31;

    int r0 = __ldg(&g_rowptr[n]);
    int r1 = __ldg(&g_rowptr[n + 1]);
    float dn = __ldg(&g_dinv[n]);
    float s = dn * dn;
    int g = __ldg(&batch[n]);

    uint2 u = __ldg(((const uint2*)(g_a1h + (size_t)n * HID)) + lane);
    float4 v = unpack_h4(u);
    float4 acc = make_float4(v.x * s, v.y * s, v.z * s, v.w * s);

    for (int j = r0; j < r1; j += 4)
        edge_chunk4(g_a1h, lane, j, r1, acc);

    float* pp = g_pool + (size_t)g * HID + lane * 4;
    asm volatile("red.global.add.v4.f32 [%0], {%1,%2,%3,%4};"
                 :: "l"(pp), "f"(acc.x), "f"(acc.y), "f"(acc.z), "f"(acc.w)
                 : "memory");
}

// ---------------- Wc = W2 @ Wfc ; Bc = b2 @ Wfc + bfc -----------------------
__global__ void k_wc(const float* __restrict__ W2, const float* __restrict__ Wfc,
                     const float* __restrict__ b2, const float* __restrict__ bfc) {
    int i = blockIdx.x;
    int j = threadIdx.x;
    float acc = 0.f;
    for (int k = 0; k < HID; k++) acc += W2[i * HID + k] * Wfc[k * HID + j];
    g_wc[i * HID + j] = acc;
    if (i == 0) {
        float a = bfc[j];
        for (int k = 0; k < HID; k++) a += b2[k] * Wfc[k * HID + j];
        g_bc[j] = a;
    }
}

// ---------------- final: out = (pool/cnt) @ Wc + Bc -------------------------
__global__ void k_out(float* __restrict__ out) {
    __shared__ float p[HID];
    int g = blockIdx.x;
    int c = threadIdx.x;
    float cnt = fmaxf(g_cnt[g], 1.f);
    p[c] = g_pool[g * HID + c] / cnt;
    __syncthreads();
    float acc = g_bc[c];
#pragma unroll 8
    for (int k = 0; k < HID; k++) acc += p[k] * g_wc[k * HID + c];
    out[g * HID + c] = acc;
}

// ---------------- launch: three-stream fork-join -----------------------------
extern "C" void kernel_launch(void* const* d_in, const int* in_sizes, int n_in,
                              void* d_out, int out_size) {
    const int*   x     = (const int*)d_in[0];
    const int*   ei    = (const int*)d_in[1];
    const int*   batch = (const int*)d_in[3];
    const float* aemb  = (const float*)d_in[4];
    const float* W1    = (const float*)d_in[6];
    const float* b1    = (const float*)d_in[7];
    const float* W2    = (const float*)d_in[8];
    const float* b2    = (const float*)d_in[9];
    const float* Wfc   = (const float*)d_in[10];
    const float* bfc   = (const float*)d_in[11];
    float* out = (float*)d_out;

    static cudaStream_t sA = nullptr, sB = nullptr, sC = nullptr;
    static cudaEvent_t eF = nullptr, eA = nullptr, eB = nullptr, eC = nullptr;
    static void *p_deg = nullptr, *p_pool = nullptr, *p_cnt = nullptr;
    if (sA == nullptr) {
        cudaStreamCreateWithFlags(&sA, cudaStreamNonBlocking);
        cudaStreamCreateWithFlags(&sB, cudaStreamNonBlocking);
        cudaStreamCreateWithFlags(&sC, cudaStreamNonBlocking);
        cudaEventCreateWithFlags(&eF, cudaEventDisableTiming);
        cudaEventCreateWithFlags(&eA, cudaEventDisableTiming);
        cudaEventCreateWithFlags(&eB, cudaEventDisableTiming);
        cudaEventCreateWithFlags(&eC, cudaEventDisableTiming);
        cudaGetSymbolAddress(&p_deg, g_deg);
        cudaGetSymbolAddress(&p_pool, g_pool);
        cudaGetSymbolAddress(&p_cnt, g_cnt);
    }

    // fork from the (captured) base stream
    cudaEventRecord(eF, 0);
    cudaStreamWaitEvent(sA, eF, 0);
    cudaStreamWaitEvent(sB, eF, 0);
    cudaStreamWaitEvent(sC, eF, 0);

    // stream A: embedding + weight precompute (critical-path candidate)
    k_embed<<<592, 256, 0, sA>>>(x, aemb, W1);
    k_wc<<<HID, HID, 0, sA>>>(W2, Wfc, b2, bfc);

    // stream B: CSR build chain
    cudaMemsetAsync(p_deg, 0, (size_t)N_NODES * sizeof(int), sB);
    k_deg<<<586, 256, 0, sB>>>(ei);
    k_scan1<<<NSB, 256, 0, sB>>>();
    k_scan23<<<(N_NODES + 511) / 512, 512, 0, sB>>>();
    k_scatter<<<(N_EDGES + 255) / 256, 256, 0, sB>>>(ei);

    // stream C: pool/cnt zero + per-graph node counts
    cudaMemsetAsync(p_pool, 0, (size_t)N_GRAPHS * HID * sizeof(float), sC);
    cudaMemsetAsync(p_cnt, 0, (size_t)N_GRAPHS * sizeof(float), sC);
    k_cnt<<<1024, 256, 0, sC>>>(batch);

    // join back to base stream
    cudaEventRecord(eA, sA);
    cudaEventRecord(eB, sB);
    cudaEventRecord(eC, sC);
    cudaStreamWaitEvent(0, eA, 0);
    cudaStreamWaitEvent(0, eB, 0);
    cudaStreamWaitEvent(0, eC, 0);

    k_pass1<<<(N_NODES + 7) / 8, 256>>>(b1);
    k_pass2<<<(N_NODES + 7) / 8, 256>>>(batch);
    k_out<<<N_GRAPHS, HID>>>(out);
}